// round 10
// baseline (speedup 1.0000x reference)
#include <cuda_runtime.h>
#include <cuda_bf16.h>
#include <cstdint>

#define Bn 32
#define Cn 512
#define Nn 1600
#define NCn 20
#define NOUT 25
#define NGRP (Bn * NCn)
#define STRIDEF 32.0f
#define CONF_T 0.3f
#define NMS_T 0.5f
#define CAPK 256
#define CAPB 192

typedef unsigned long long ull;

// ---------------- scratch -----------------------------------------------------
__device__ float g_boxes[Bn * Nn * 4];
__device__ int   g_cnt[NGRP];
__device__ ull   g_keys[NGRP * CAPK];

// ---------------- helpers -----------------------------------------------------
__device__ __forceinline__ uint32_t bf16x2_of(float lo, float hi) {
    uint32_t r;
    asm("cvt.rn.bf16x2.f32 %0, %1, %2;" : "=r"(r) : "f"(hi), "f"(lo));
    return r;   // low 16 bits = lo, high 16 bits = hi
}
__device__ __forceinline__ float sigmoidf_(float x) { return 1.0f / (1.0f + expf(-x)); }

__device__ __forceinline__ void mma_bf16(float* d, const uint32_t* a,
                                         uint32_t b0, uint32_t b1) {
    asm volatile(
        "mma.sync.aligned.m16n8k16.row.col.f32.bf16.bf16.f32 "
        "{%0,%1,%2,%3}, {%4,%5,%6,%7}, {%8,%9}, {%0,%1,%2,%3};"
        : "+f"(d[0]), "+f"(d[1]), "+f"(d[2]), "+f"(d[3])
        : "r"(a[0]), "r"(a[1]), "r"(a[2]), "r"(a[3]), "r"(b0), "r"(b1));
}

// SMEM float offsets
#define F_BIAS 0            // 32 floats
#define F_AH   32           // 128*33 u32 = 4224
#define F_AL   (F_AH + 4224)
#define F_BH   (F_AL + 4224)  // 32*257 = 8224
#define F_BL   (F_BH + 8224)
#define F_TOTAL (F_BL + 8224) // 24928 floats = 99712 B
#define F_DSM  F_AH         // D exchange reuses A region (needs 4352 <= 8448)

// ---------------- Kernel A: mma.sync bf16 hi/lo 3-pass head ------------------
// grid = 32 batches x 13 tiles (tile 12: 64 valid cells). 128 threads.
// Warp w: rows [w*32, w*32+32) (2 m16 tiles) x 32 outs (4 n8 tiles).
extern __shared__ float smemA[];

__global__ void __launch_bounds__(128) head_kernel(
    const float* __restrict__ feat,
    const float* __restrict__ wo, const float* __restrict__ bo,
    const float* __restrict__ wc, const float* __restrict__ bc,
    const float* __restrict__ wr, const float* __restrict__ br,
    float* __restrict__ out)
{
    const int tid  = threadIdx.x;
    const int wid  = tid >> 5;
    const int lane = tid & 31;
    const int grp  = lane >> 2;          // 0..7
    const int qid  = lane & 3;           // 0..3

    uint32_t* Ah = (uint32_t*)(smemA + F_AH);
    uint32_t* Al = (uint32_t*)(smemA + F_AL);
    uint32_t* Bh = (uint32_t*)(smemA + F_BH);
    uint32_t* Bl = (uint32_t*)(smemA + F_BL);
    float*    bias = smemA + F_BIAS;

    // ---- stage B once: Bh/Bl[n*257 + kp] = bf16x2(W[n][2kp], W[n][2kp+1])
    for (int i = tid; i < 32 * 256; i += 128) {
        int n = i >> 8, kp = i & 255;
        float2 wv = make_float2(0.f, 0.f);
        if (n == 0)       wv = ((const float2*)wo)[kp];
        else if (n <= 20) wv = ((const float2*)(wc + (n - 1) * Cn))[kp];
        else if (n <= 24) wv = ((const float2*)(wr + (n - 21) * Cn))[kp];
        uint32_t hp = bf16x2_of(wv.x, wv.y);
        float h0 = __uint_as_float(hp << 16);
        float h1 = __uint_as_float(hp & 0xFFFF0000u);
        uint32_t lp = bf16x2_of(wv.x - h0, wv.y - h1);
        Bh[n * 257 + kp] = hp;
        Bl[n * 257 + kp] = lp;
    }
    if (tid < NOUT) {
        float v;
        if (tid == 0)        v = bo[0];
        else if (tid <= NCn) v = bc[tid - 1];
        else                 v = br[tid - 1 - NCn];
        bias[tid] = v;
    }

    const int bb = blockIdx.x / 13;
    const int tt = blockIdx.x - bb * 13;
    const int n0 = tt * 128;
    const int nvalid = (tt < 12) ? 128 : 64;
    const int cellc = n0 + ((tid < nvalid) ? tid : (nvalid - 1));
    const float* fpc = feat + (size_t)bb * Cn * Nn + cellc;

    float d[2][4][4];
#pragma unroll
    for (int mt = 0; mt < 2; mt++)
#pragma unroll
        for (int nt = 0; nt < 4; nt++)
#pragma unroll
            for (int r = 0; r < 4; r++) d[mt][nt][r] = 0.0f;

    const int mb = wid * 32;

#pragma unroll 1
    for (int chunk = 0; chunk < 8; chunk++) {
        const int c0 = chunk * 64;
        __syncthreads();   // prior chunk's mma done before overwrite (no-op on first)
        // ---- stage A chunk: thread t = cell row t
#pragma unroll 4
        for (int kp = 0; kp < 32; kp++) {
            float v0 = fpc[(c0 + 2 * kp) * Nn];
            float v1 = fpc[(c0 + 2 * kp + 1) * Nn];
            uint32_t hp = bf16x2_of(v0, v1);
            float h0 = __uint_as_float(hp << 16);
            float h1 = __uint_as_float(hp & 0xFFFF0000u);
            uint32_t lp = bf16x2_of(v0 - h0, v1 - h1);
            Ah[tid * 33 + kp] = hp;
            Al[tid * 33 + kp] = lp;
        }
        __syncthreads();

        // ---- mma: 4 k16-steps
#pragma unroll
        for (int s = 0; s < 4; s++) {
            const int ka = s * 8 + qid;            // chunk-local A kp
            const int kb = chunk * 32 + s * 8 + qid;
            uint32_t ah[2][4], al[2][4];
#pragma unroll
            for (int mt = 0; mt < 2; mt++) {
                int r0 = mb + mt * 16 + grp;
                ah[mt][0] = Ah[r0 * 33 + ka];
                ah[mt][1] = Ah[(r0 + 8) * 33 + ka];
                ah[mt][2] = Ah[r0 * 33 + ka + 4];
                ah[mt][3] = Ah[(r0 + 8) * 33 + ka + 4];
                al[mt][0] = Al[r0 * 33 + ka];
                al[mt][1] = Al[(r0 + 8) * 33 + ka];
                al[mt][2] = Al[r0 * 33 + ka + 4];
                al[mt][3] = Al[(r0 + 8) * 33 + ka + 4];
            }
#pragma unroll
            for (int nt = 0; nt < 4; nt++) {
                int nb = (nt * 8 + grp) * 257 + kb;
                uint32_t bh0 = Bh[nb], bh1 = Bh[nb + 4];
                uint32_t bl0 = Bl[nb], bl1 = Bl[nb + 4];
#pragma unroll
                for (int mt = 0; mt < 2; mt++) {
                    mma_bf16(d[mt][nt], ah[mt], bh0, bh1);   // Ah*Bh
                    mma_bf16(d[mt][nt], al[mt], bh0, bh1);   // Al*Bh
                    mma_bf16(d[mt][nt], ah[mt], bl0, bl1);   // Ah*Bl
                }
            }
        }
    }
    __syncthreads();

    // ---- exchange D through smem (reuse A region): Dsm[row*34 + col]
    float* Dsm = smemA + F_DSM;
#pragma unroll
    for (int mt = 0; mt < 2; mt++) {
        int r0 = mb + mt * 16 + grp;
#pragma unroll
        for (int nt = 0; nt < 4; nt++) {
            int c = nt * 8 + qid * 2;
            *(float2*)&Dsm[r0 * 34 + c]       = make_float2(d[mt][nt][0], d[mt][nt][1]);
            *(float2*)&Dsm[(r0 + 8) * 34 + c] = make_float2(d[mt][nt][2], d[mt][nt][3]);
        }
    }
    __syncthreads();

    // ---- epilogue: thread = cell
    if (tid < nvalid) {
        int n = n0 + tid;
        float rr[25];
#pragma unroll
        for (int j = 0; j < 12; j++) {
            float2 v = *(const float2*)&Dsm[tid * 34 + 2 * j];
            rr[2 * j]     = v.x + bias[2 * j];
            rr[2 * j + 1] = v.y + bias[2 * j + 1];
        }
        rr[24] = Dsm[tid * 34 + 24] + bias[24];

        float sig_obj = sigmoidf_(rr[0]);
        float best = rr[1]; int lab = 0;
#pragma unroll
        for (int k = 1; k < NCn; k++)
            if (rr[1 + k] > best) { best = rr[1 + k]; lab = k; }
        float score = sqrtf(sig_obj * sigmoidf_(best));

        float gx = (float)(n % 40), gy = (float)(n / 40);
        float cx = (sigmoidf_(rr[21]) + gx) * STRIDEF;
        float cy = (sigmoidf_(rr[22]) + gy) * STRIDEF;
        float bw = expf(rr[23]) * STRIDEF;
        float bh = expf(rr[24]) * STRIDEF;

        int idx = bb * Nn + n;
        float4 bx = make_float4(cx - bw * 0.5f, cy - bh * 0.5f,
                                cx + bw * 0.5f, cy + bh * 0.5f);
        *(float4*)&g_boxes[idx * 4] = bx;
        out[Bn * Nn * 5 + idx] = (float)lab;

        int g = bb * NCn + lab;
        int pos = atomicAdd(&g_cnt[g], 1);
        unsigned sbits = __float_as_uint(score);
        if (pos < CAPK)
            g_keys[g * CAPK + pos] = ((ull)(~sbits) << 32) | (unsigned)n;
    }
}

// ---------------- Kernel B: block-per-group bitmask NMS (unchanged R8) ------
__global__ void __launch_bounds__(128) nms_kernel(float* __restrict__ out)
{
    __shared__ ull    k[CAPK];
    __shared__ float4 bx[CAPB];
    __shared__ ull    mk[CAPB * 3];
    __shared__ int    scnt;

    const int tid = threadIdx.x;
    const int grp = blockIdx.x;
    const int b   = grp / NCn;
    const int bIdx = b * Nn;

    int M = g_cnt[grp];
    if (M > CAPB) M = CAPB;
    if (tid == 0) scnt = 0;

    for (int t = tid; t < M; t += 128) k[t] = g_keys[grp * CAPK + t];
    int P = 1; while (P < M) P <<= 1;
    for (int i = M + tid; i < P; i += 128) k[i] = ~0ULL;
    __syncthreads();
    if (tid == 0) g_cnt[grp] = 0;

    for (int kk = 2; kk <= P; kk <<= 1) {
        for (int j = kk >> 1; j > 0; j >>= 1) {
            for (int i = tid; i < P; i += 128) {
                int x = i ^ j;
                if (x > i) {
                    bool up = ((i & kk) == 0);
                    ull a = k[i], c = k[x];
                    if ((a > c) == up) { k[i] = c; k[x] = a; }
                }
            }
            __syncthreads();
        }
    }

    int mc_loc = 0;
    for (int t = tid; t < M; t += 128) {
        int n = (int)(k[t] & 0xFFFFFFFFULL);
        bx[t] = *(const float4*)&g_boxes[(bIdx + n) * 4];
        float s = __uint_as_float(~(unsigned)(k[t] >> 32));
        if (s > CONF_T) mc_loc++;
    }
    if (mc_loc) atomicAdd(&scnt, mc_loc);
    __syncthreads();
    const int Mc = scnt;

    for (int t = tid; t < M; t += 128) {
        ull m0 = 0, m1 = 0, m2 = 0;
        float4 A = bx[t];
        float areaA = (A.z - A.x) * (A.w - A.y);
        for (int j = t + 1; j < M; j++) {
            float4 Bv = bx[j];
            float x1 = fmaxf(A.x, Bv.x), y1 = fmaxf(A.y, Bv.y);
            float x2 = fminf(A.z, Bv.z), y2 = fminf(A.w, Bv.w);
            float inter = fmaxf(x2 - x1, 0.0f) * fmaxf(y2 - y1, 0.0f);
            float areaB = (Bv.z - Bv.x) * (Bv.w - Bv.y);
            float uni = areaA + areaB - inter;
            bool sup = inter > NMS_T * uni;
            ull bit = sup ? (1ULL << (j & 63)) : 0ULL;
            if (j < 64)       m0 |= bit;
            else if (j < 128) m1 |= bit;
            else              m2 |= bit;
        }
        mk[t * 3 + 0] = m0; mk[t * 3 + 1] = m1; mk[t * 3 + 2] = m2;
    }
    __syncthreads();

    ull kp0 = (Mc <= 0) ? 0ULL : (Mc >= 64 ? ~0ULL : ((1ULL << Mc) - 1));
    int c1 = Mc - 64;
    ull kp1 = (c1 <= 0) ? 0ULL : (c1 >= 64 ? ~0ULL : ((1ULL << c1) - 1));
    int c2 = Mc - 128;
    ull kp2 = (c2 <= 0) ? 0ULL : (c2 >= 64 ? ~0ULL : ((1ULL << c2) - 1));

#pragma unroll 4
    for (int i = 0; i < Mc; i++) {
        ull m0 = mk[i * 3 + 0], m1 = mk[i * 3 + 1], m2 = mk[i * 3 + 2];
        ull kw = (i < 64) ? kp0 : (i < 128) ? kp1 : kp2;
        if ((kw >> (i & 63)) & 1ULL) {
            kp0 &= ~m0; kp1 &= ~m1; kp2 &= ~m2;
        }
    }

    for (int t = tid; t < M; t += 128) {
        int n = (int)(k[t] & 0xFFFFFFFFULL);
        int idx = bIdx + n;
        ull kw = (t < 64) ? kp0 : (t < 128) ? kp1 : kp2;
        bool kept = (kw >> (t & 63)) & 1ULL;
        float s = __uint_as_float(~(unsigned)(k[t] >> 32));
        float4 Bv = bx[t];
        out[idx * 5 + 0] = kept ? Bv.x : 0.0f;
        out[idx * 5 + 1] = kept ? Bv.y : 0.0f;
        out[idx * 5 + 2] = kept ? Bv.z : 0.0f;
        out[idx * 5 + 3] = kept ? Bv.w : 0.0f;
        out[idx * 5 + 4] = kept ? s : 0.0f;
        out[Bn * Nn * 6 + idx] = kept ? 1.0f : 0.0f;
    }
}

// ---------------- launch -----------------------------------------------------
extern "C" void kernel_launch(void* const* d_in, const int* in_sizes, int n_in,
                              void* d_out, int out_size)
{
    const float* feat = (const float*)d_in[0];
    const float* wo   = (const float*)d_in[1];
    const float* bo   = (const float*)d_in[2];
    const float* wc   = (const float*)d_in[3];
    const float* bc   = (const float*)d_in[4];
    const float* wr   = (const float*)d_in[5];
    const float* br   = (const float*)d_in[6];
    float* out = (float*)d_out;

    size_t smem = (size_t)F_TOTAL * sizeof(float);   // 99712 B
    cudaFuncSetAttribute(head_kernel,
                         cudaFuncAttributeMaxDynamicSharedMemorySize, (int)smem);

    head_kernel<<<Bn * 13, 128, smem>>>(feat, wo, bo, wc, bc, wr, br, out);
    nms_kernel<<<NGRP, 128>>>(out);
}

// round 11
// speedup vs baseline: 1.5843x; 1.5843x over previous
#include <cuda_runtime.h>
#include <cstdint>

#define Bn 32
#define Cn 512
#define Nn 1600
#define NCn 20
#define NOUT 25
#define NGRP (Bn * NCn)
#define STRIDEF 32.0f
#define CONF_T 0.3f
#define NMS_T 0.5f
#define CAPK 256
#define CAPB 192

typedef unsigned long long ull;

// ---------------- scratch (device globals; zero-initialized at load) --------
__device__ float g_boxes[Bn * Nn * 4];
__device__ int   g_cnt[NGRP];
__device__ ull   g_keys[NGRP * CAPK];

// ---------------- helpers ----------------------------------------------------
__device__ __forceinline__ ull pack2(float x, float y) {
    ull r; asm("mov.b64 %0, {%1, %2};" : "=l"(r) : "f"(x), "f"(y)); return r;
}
__device__ __forceinline__ void fma2(ull& d, ull a, ull b) {
    asm("fma.rn.f32x2 %0, %1, %2, %0;" : "+l"(d) : "l"(a), "l"(b));
}
__device__ __forceinline__ float2 unpack2(ull v) {
    float2 r; asm("mov.b64 {%0, %1}, %2;" : "=f"(r.x), "=f"(r.y) : "l"(v)); return r;
}
__device__ __forceinline__ float sigmoidf_(float x) { return 1.0f / (1.0f + expf(-x)); }

// ---------------- Kernel A: head, 2 cells/thread x split-K(4), 256 thr ------
// 400 blocks x 256 threads (3200 warps, 5.4/SMSP). Thread (q = tid>>6,
// slot = tid&63): channels [q*128, q*128+128), cells blockIdx*128 + slot*2,+1.
// 13 LDS.64 weight pairs feed 26 FFMA2. Quarters combined via recycled smem
// (partial stride 27 to avoid bank conflicts).
extern __shared__ float smemA[];
#define TBH 256
#define P_STRIDE 27
#define P_Q      3456          // 128 cells * 27
#define F_BIAS   13824         // after 4*3456 partial region (weights use 13312)
#define F_TOTAL  13856         // floats -> 55424 B

__global__ void __launch_bounds__(TBH) head_kernel(
    const float* __restrict__ feat,
    const float* __restrict__ wo, const float* __restrict__ bo,
    const float* __restrict__ wc, const float* __restrict__ bc,
    const float* __restrict__ wr, const float* __restrict__ br,
    float* __restrict__ out)
{
    float* ws   = smemA;               // weights [c*26 + o]
    float* bias = smemA + F_BIAS;
    const int tid = threadIdx.x;

    for (int i = tid; i < (Cn / 4) * NOUT; i += TBH) {
        int o  = i >> 7;               // 0..24
        int cq = i & 127;
        const float* row;
        if (o == 0)       row = wo;
        else if (o <= 20) row = wc + (o - 1) * Cn;
        else              row = wr + (o - 21) * Cn;
        float4 w4 = ((const float4*)row)[cq];
        int c = cq * 4;
        ws[(c + 0) * 26 + o] = w4.x;
        ws[(c + 1) * 26 + o] = w4.y;
        ws[(c + 2) * 26 + o] = w4.z;
        ws[(c + 3) * 26 + o] = w4.w;
    }
    for (int c = tid; c < Cn; c += TBH) ws[c * 26 + 25] = 0.0f;  // pad slot
    if (tid < NOUT) {
        float v;
        if (tid == 0)        v = bo[0];
        else if (tid <= NCn) v = bc[tid - 1];
        else                 v = br[tid - 1 - NCn];
        bias[tid] = v;
    }
    __syncthreads();

    const int q    = tid >> 6;                      // K-quarter
    const int slot = tid & 63;                      // cell-pair slot
    const int cell0 = blockIdx.x * 128 + slot * 2;  // even; pair stays in batch
    const int b  = cell0 / Nn;
    const int n0 = cell0 - b * Nn;
    const float2* fp2 = (const float2*)(feat + (size_t)b * Cn * Nn
                                             + (size_t)q * 128 * Nn + n0);
    const ull* wp = (const ull*)ws;                 // pair p of channel c: wp[c*13+p]
    const int cb = q * 128;

    ull acc[2][13];
#pragma unroll
    for (int cc = 0; cc < 2; cc++)
#pragma unroll
        for (int p = 0; p < 13; p++) acc[cc][p] = 0ULL;

#pragma unroll 1
    for (int c0 = 0; c0 < 128; c0 += 8) {
        float2 v[8];
#pragma unroll
        for (int u = 0; u < 8; u++) v[u] = fp2[(c0 + u) * (Nn / 2)];
#pragma unroll
        for (int u = 0; u < 8; u++) {
            ull xx = pack2(v[u].x, v[u].x);
            ull yy = pack2(v[u].y, v[u].y);
            int base = (cb + c0 + u) * 13;
#pragma unroll
            for (int p = 0; p < 13; p++) {
                ull w = wp[base + p];
                fma2(acc[0][p], xx, w);
                fma2(acc[1][p], yy, w);
            }
        }
    }

    // dump partials into recycled weight region: part[q*3456 + cl*27 + o]
    __syncthreads();
#pragma unroll
    for (int cc = 0; cc < 2; cc++) {
        int cl = slot * 2 + cc;                 // cell_local 0..127
        float* dst = smemA + q * P_Q + cl * P_STRIDE;
#pragma unroll
        for (int p = 0; p < 13; p++) {
            float2 t = unpack2(acc[cc][p]);
            dst[2 * p] = t.x;
            if (2 * p + 1 < NOUT) dst[2 * p + 1] = t.y;
        }
    }
    __syncthreads();

    // epilogue: one cell per thread (threads 0..127)
    if (tid < 128) {
        int cl = tid;
        int cell = blockIdx.x * 128 + cl;
        int eb = cell / Nn;
        int n  = cell - eb * Nn;
        float rr[25];
#pragma unroll
        for (int o = 0; o < NOUT; o++)
            rr[o] = smemA[0 * P_Q + cl * P_STRIDE + o]
                  + smemA[1 * P_Q + cl * P_STRIDE + o]
                  + smemA[2 * P_Q + cl * P_STRIDE + o]
                  + smemA[3 * P_Q + cl * P_STRIDE + o]
                  + bias[o];

        float sig_obj = sigmoidf_(rr[0]);
        float best = rr[1]; int lab = 0;
#pragma unroll
        for (int k = 1; k < NCn; k++)
            if (rr[1 + k] > best) { best = rr[1 + k]; lab = k; }
        float score = sqrtf(sig_obj * sigmoidf_(best));

        float gx = (float)(n % 40), gy = (float)(n / 40);
        float cx = (sigmoidf_(rr[21]) + gx) * STRIDEF;
        float cy = (sigmoidf_(rr[22]) + gy) * STRIDEF;
        float bw = expf(rr[23]) * STRIDEF;
        float bh = expf(rr[24]) * STRIDEF;

        int idx = eb * Nn + n;
        float4 bx = make_float4(cx - bw * 0.5f, cy - bh * 0.5f,
                                cx + bw * 0.5f, cy + bh * 0.5f);
        *(float4*)&g_boxes[idx * 4] = bx;
        out[Bn * Nn * 5 + idx] = (float)lab;    // labels region

        int grp = eb * NCn + lab;
        int pos = atomicAdd(&g_cnt[grp], 1);
        unsigned sb = __float_as_uint(score);   // score > 0 always
        if (pos < CAPK)
            g_keys[grp * CAPK + pos] = ((ull)(~sb) << 32) | (unsigned)n;
    }
}

// ---------------- Kernel B: block-per-group NMS, rank sort + bitmasks -------
__global__ void __launch_bounds__(128) nms_kernel(float* __restrict__ out)
{
    __shared__ ull    k[CAPK];
    __shared__ ull    ks[CAPB];        // rank-sorted keys
    __shared__ float4 bx[CAPB];
    __shared__ ull    mk[CAPB * 3];
    __shared__ int    scnt;

    const int tid = threadIdx.x;
    const int grp = blockIdx.x;
    const int b   = grp / NCn;
    const int bIdx = b * Nn;

    int M = g_cnt[grp];                // all threads read first
    if (M > CAPB) M = CAPB;
    if (tid == 0) scnt = 0;

    for (int t = tid; t < M; t += 128) k[t] = g_keys[grp * CAPK + t];
    __syncthreads();                   // everyone has read g_cnt
    if (tid == 0) g_cnt[grp] = 0;      // re-arm after barrier

    // rank sort: keys unique (distinct n in low bits) -> rank is a permutation
    for (int t = tid; t < M; t += 128) {
        ull key = k[t];
        int r = 0;
#pragma unroll 4
        for (int j = 0; j < M; j++)    // k[j] broadcast LDS
            r += (k[j] < key) ? 1 : 0;
        ks[r] = key;
    }
    __syncthreads();

    // gather boxes in rank order; count conf-passing (prefix of sorted order)
    int mc_loc = 0;
    for (int t = tid; t < M; t += 128) {
        int n = (int)(ks[t] & 0xFFFFFFFFULL);
        bx[t] = *(const float4*)&g_boxes[(bIdx + n) * 4];
        float s = __uint_as_float(~(unsigned)(ks[t] >> 32));
        if (s > CONF_T) mc_loc++;
    }
    if (mc_loc) atomicAdd(&scnt, mc_loc);
    __syncthreads();
    const int Mc = scnt;

    // suppression bitmasks; uniform j loop -> bx[j] is broadcast LDS.128
    for (int t = tid; t < M; t += 128) {
        ull m0 = 0, m1 = 0, m2 = 0;
        float4 A = bx[t];
        float areaA = (A.z - A.x) * (A.w - A.y);
#pragma unroll 4
        for (int j = 0; j < M; j++) {
            float4 Bv = bx[j];
            float x1 = fmaxf(A.x, Bv.x), y1 = fmaxf(A.y, Bv.y);
            float x2 = fminf(A.z, Bv.z), y2 = fminf(A.w, Bv.w);
            float inter = fmaxf(x2 - x1, 0.0f) * fmaxf(y2 - y1, 0.0f);
            float areaB = (Bv.z - Bv.x) * (Bv.w - Bv.y);
            float uni = areaA + areaB - inter;
            bool sup = (j > t) && (inter > NMS_T * uni);
            ull bit = sup ? (1ULL << (j & 63)) : 0ULL;
            if (j < 64)       m0 |= bit;
            else if (j < 128) m1 |= bit;
            else              m2 |= bit;
        }
        mk[t * 3 + 0] = m0; mk[t * 3 + 1] = m1; mk[t * 3 + 2] = m2;
    }
    __syncthreads();

    // serial mask reduction, replicated on all threads (broadcast LDS)
    ull kp0 = (Mc <= 0) ? 0ULL : (Mc >= 64 ? ~0ULL : ((1ULL << Mc) - 1));
    int c1 = Mc - 64;
    ull kp1 = (c1 <= 0) ? 0ULL : (c1 >= 64 ? ~0ULL : ((1ULL << c1) - 1));
    int c2 = Mc - 128;
    ull kp2 = (c2 <= 0) ? 0ULL : (c2 >= 64 ? ~0ULL : ((1ULL << c2) - 1));

#pragma unroll 4
    for (int i = 0; i < Mc; i++) {
        ull m0 = mk[i * 3 + 0], m1 = mk[i * 3 + 1], m2 = mk[i * 3 + 2];
        ull kw = (i < 64) ? kp0 : (i < 128) ? kp1 : kp2;
        if ((kw >> (i & 63)) & 1ULL) {
            kp0 &= ~m0; kp1 &= ~m1; kp2 &= ~m2;
        }
    }

    // compose outputs
    for (int t = tid; t < M; t += 128) {
        int n = (int)(ks[t] & 0xFFFFFFFFULL);
        int idx = bIdx + n;
        ull kw = (t < 64) ? kp0 : (t < 128) ? kp1 : kp2;
        bool kept = (kw >> (t & 63)) & 1ULL;
        float s = __uint_as_float(~(unsigned)(ks[t] >> 32));
        float4 Bv = bx[t];
        out[idx * 5 + 0] = kept ? Bv.x : 0.0f;
        out[idx * 5 + 1] = kept ? Bv.y : 0.0f;
        out[idx * 5 + 2] = kept ? Bv.z : 0.0f;
        out[idx * 5 + 3] = kept ? Bv.w : 0.0f;
        out[idx * 5 + 4] = kept ? s : 0.0f;
        out[Bn * Nn * 6 + idx] = kept ? 1.0f : 0.0f;   // keep region
    }
}

// ---------------- launch -----------------------------------------------------
extern "C" void kernel_launch(void* const* d_in, const int* in_sizes, int n_in,
                              void* d_out, int out_size)
{
    const float* feat = (const float*)d_in[0];
    const float* wo   = (const float*)d_in[1];
    const float* bo   = (const float*)d_in[2];
    const float* wc   = (const float*)d_in[3];
    const float* bc   = (const float*)d_in[4];
    const float* wr   = (const float*)d_in[5];
    const float* br   = (const float*)d_in[6];
    float* out = (float*)d_out;

    size_t smem = (size_t)F_TOTAL * sizeof(float);   // 55424 B
    cudaFuncSetAttribute(head_kernel,
                         cudaFuncAttributeMaxDynamicSharedMemorySize, (int)smem);

    head_kernel<<<400, TBH, smem>>>(feat, wo, bo, wc, bc, wr, br, out);
    nms_kernel<<<NGRP, 128>>>(out);
}

// round 12
// speedup vs baseline: 1.8670x; 1.1784x over previous
#include <cuda_runtime.h>
#include <cstdint>

#define Bn 32
#define Cn 512
#define Nn 1600
#define NCn 20
#define NOUT 25
#define NGRP (Bn * NCn)
#define STRIDEF 32.0f
#define CONF_T 0.3f
#define NMS_T 0.5f
#define CAPK 256
#define CAPB 192

typedef unsigned long long ull;

// ---------------- scratch (device globals; zero-initialized at load) --------
__device__ float g_boxes[Bn * Nn * 4];
__device__ int   g_cnt[NGRP];
__device__ ull   g_keys[NGRP * CAPK];

// ---------------- helpers ----------------------------------------------------
__device__ __forceinline__ ull pack2(float x, float y) {
    ull r; asm("mov.b64 %0, {%1, %2};" : "=l"(r) : "f"(x), "f"(y)); return r;
}
__device__ __forceinline__ void fma2(ull& d, ull a, ull b) {
    asm("fma.rn.f32x2 %0, %1, %2, %0;" : "+l"(d) : "l"(a), "l"(b));
}
__device__ __forceinline__ float2 unpack2(ull v) {
    float2 r; asm("mov.b64 {%0, %1}, %2;" : "=f"(r.x), "=f"(r.y) : "l"(v)); return r;
}
__device__ __forceinline__ float sigmoidf_(float x) { return 1.0f / (1.0f + expf(-x)); }

// ---------------- Kernel A: head, 2 cells/thread x split-K(4), 256 thr ------
// Weight smem layout: ws[c*28 + o], 112 B/channel, quads 16B-aligned ->
// per channel: 6x LDS.128 (12 output pairs) + 1x LDS.32 (output 24).
// Per channel-pair issues: 6+1 LDS + 24 FFMA2 + 2 FFMA + 2 pack (vs 41 before).
extern __shared__ float smemA[];
#define TBH 256
#define W_STRIDE 28
#define P_STRIDE 27
#define P_Q      3456          // 128 cells * 27
#define F_PART_BASE 0
#define F_BIAS   14336         // weights use 512*28 = 14336 floats
#define F_TOTAL  14368         // floats -> 57472 B

__global__ void __launch_bounds__(TBH) head_kernel(
    const float* __restrict__ feat,
    const float* __restrict__ wo, const float* __restrict__ bo,
    const float* __restrict__ wc, const float* __restrict__ bc,
    const float* __restrict__ wr, const float* __restrict__ br,
    float* __restrict__ out)
{
    float* ws   = smemA;               // weights [c*28 + o]
    float* bias = smemA + F_BIAS;
    const int tid = threadIdx.x;

    for (int i = tid; i < (Cn / 4) * NOUT; i += TBH) {
        int o  = i >> 7;               // 0..24
        int cq = i & 127;
        const float* row;
        if (o == 0)       row = wo;
        else if (o <= 20) row = wc + (o - 1) * Cn;
        else              row = wr + (o - 21) * Cn;
        float4 w4 = ((const float4*)row)[cq];
        int c = cq * 4;
        ws[(c + 0) * W_STRIDE + o] = w4.x;
        ws[(c + 1) * W_STRIDE + o] = w4.y;
        ws[(c + 2) * W_STRIDE + o] = w4.z;
        ws[(c + 3) * W_STRIDE + o] = w4.w;
    }
    if (tid < NOUT) {
        float v;
        if (tid == 0)        v = bo[0];
        else if (tid <= NCn) v = bc[tid - 1];
        else                 v = br[tid - 1 - NCn];
        bias[tid] = v;
    }
    __syncthreads();

    const int q    = tid >> 6;                      // K-quarter
    const int slot = tid & 63;                      // cell-pair slot
    const int cell0 = blockIdx.x * 128 + slot * 2;  // even; pair stays in batch
    const int b  = cell0 / Nn;
    const int n0 = cell0 - b * Nn;
    const float2* fp2 = (const float2*)(feat + (size_t)b * Cn * Nn
                                             + (size_t)q * 128 * Nn + n0);
    const int cb = q * 128;

    ull acc[2][12];                     // 12 output pairs per cell
    float a24[2] = {0.0f, 0.0f};        // output 24
#pragma unroll
    for (int cc = 0; cc < 2; cc++)
#pragma unroll
        for (int p = 0; p < 12; p++) acc[cc][p] = 0ULL;

#pragma unroll 1
    for (int c0 = 0; c0 < 128; c0 += 8) {
        float2 v[8];
#pragma unroll
        for (int u = 0; u < 8; u++) v[u] = fp2[(c0 + u) * (Nn / 2)];
#pragma unroll
        for (int u = 0; u < 8; u++) {
            ull xx = pack2(v[u].x, v[u].x);
            ull yy = pack2(v[u].y, v[u].y);
            const float* wc_ = ws + (cb + c0 + u) * W_STRIDE;
#pragma unroll
            for (int qd = 0; qd < 6; qd++) {
                // one LDS.128 = two output-pairs for this channel
                const uint4 w4 = *(const uint4*)(wc_ + qd * 4);
                ull w01 = ((ull)w4.y << 32) | w4.x;
                ull w23 = ((ull)w4.w << 32) | w4.z;
                fma2(acc[0][2 * qd],     xx, w01);
                fma2(acc[1][2 * qd],     yy, w01);
                fma2(acc[0][2 * qd + 1], xx, w23);
                fma2(acc[1][2 * qd + 1], yy, w23);
            }
            float w24 = wc_[24];
            a24[0] = fmaf(v[u].x, w24, a24[0]);
            a24[1] = fmaf(v[u].y, w24, a24[1]);
        }
    }

    // dump partials into recycled weight region: part[q*3456 + cl*27 + o]
    __syncthreads();
#pragma unroll
    for (int cc = 0; cc < 2; cc++) {
        int cl = slot * 2 + cc;                 // cell_local 0..127
        float* dst = smemA + F_PART_BASE + q * P_Q + cl * P_STRIDE;
#pragma unroll
        for (int p = 0; p < 12; p++) {
            float2 t = unpack2(acc[cc][p]);
            dst[2 * p]     = t.x;
            dst[2 * p + 1] = t.y;
        }
        dst[24] = a24[cc];
    }
    __syncthreads();

    // epilogue: one cell per thread (threads 0..127)
    if (tid < 128) {
        int cl = tid;
        int cell = blockIdx.x * 128 + cl;
        int eb = cell / Nn;
        int n  = cell - eb * Nn;
        float rr[25];
#pragma unroll
        for (int o = 0; o < NOUT; o++)
            rr[o] = smemA[F_PART_BASE + 0 * P_Q + cl * P_STRIDE + o]
                  + smemA[F_PART_BASE + 1 * P_Q + cl * P_STRIDE + o]
                  + smemA[F_PART_BASE + 2 * P_Q + cl * P_STRIDE + o]
                  + smemA[F_PART_BASE + 3 * P_Q + cl * P_STRIDE + o]
                  + bias[o];

        float sig_obj = sigmoidf_(rr[0]);
        float best = rr[1]; int lab = 0;
#pragma unroll
        for (int k = 1; k < NCn; k++)
            if (rr[1 + k] > best) { best = rr[1 + k]; lab = k; }
        float score = sqrtf(sig_obj * sigmoidf_(best));

        float gx = (float)(n % 40), gy = (float)(n / 40);
        float cx = (sigmoidf_(rr[21]) + gx) * STRIDEF;
        float cy = (sigmoidf_(rr[22]) + gy) * STRIDEF;
        float bw = expf(rr[23]) * STRIDEF;
        float bh = expf(rr[24]) * STRIDEF;

        int idx = eb * Nn + n;
        float4 bx = make_float4(cx - bw * 0.5f, cy - bh * 0.5f,
                                cx + bw * 0.5f, cy + bh * 0.5f);
        *(float4*)&g_boxes[idx * 4] = bx;
        out[Bn * Nn * 5 + idx] = (float)lab;    // labels region

        int grp = eb * NCn + lab;
        int pos = atomicAdd(&g_cnt[grp], 1);
        unsigned sb = __float_as_uint(score);   // score > 0 always
        if (pos < CAPK)
            g_keys[grp * CAPK + pos] = ((ull)(~sb) << 32) | (unsigned)n;
    }
}

// ---------------- Kernel B: block-per-group NMS (unchanged R11) -------------
__global__ void __launch_bounds__(128) nms_kernel(float* __restrict__ out)
{
    __shared__ ull    k[CAPK];
    __shared__ ull    ks[CAPB];
    __shared__ float4 bx[CAPB];
    __shared__ ull    mk[CAPB * 3];
    __shared__ int    scnt;

    const int tid = threadIdx.x;
    const int grp = blockIdx.x;
    const int b   = grp / NCn;
    const int bIdx = b * Nn;

    int M = g_cnt[grp];
    if (M > CAPB) M = CAPB;
    if (tid == 0) scnt = 0;

    for (int t = tid; t < M; t += 128) k[t] = g_keys[grp * CAPK + t];
    __syncthreads();
    if (tid == 0) g_cnt[grp] = 0;

    // rank sort (keys unique)
    for (int t = tid; t < M; t += 128) {
        ull key = k[t];
        int r = 0;
#pragma unroll 4
        for (int j = 0; j < M; j++)
            r += (k[j] < key) ? 1 : 0;
        ks[r] = key;
    }
    __syncthreads();

    int mc_loc = 0;
    for (int t = tid; t < M; t += 128) {
        int n = (int)(ks[t] & 0xFFFFFFFFULL);
        bx[t] = *(const float4*)&g_boxes[(bIdx + n) * 4];
        float s = __uint_as_float(~(unsigned)(ks[t] >> 32));
        if (s > CONF_T) mc_loc++;
    }
    if (mc_loc) atomicAdd(&scnt, mc_loc);
    __syncthreads();
    const int Mc = scnt;

    for (int t = tid; t < M; t += 128) {
        ull m0 = 0, m1 = 0, m2 = 0;
        float4 A = bx[t];
        float areaA = (A.z - A.x) * (A.w - A.y);
#pragma unroll 4
        for (int j = 0; j < M; j++) {
            float4 Bv = bx[j];
            float x1 = fmaxf(A.x, Bv.x), y1 = fmaxf(A.y, Bv.y);
            float x2 = fminf(A.z, Bv.z), y2 = fminf(A.w, Bv.w);
            float inter = fmaxf(x2 - x1, 0.0f) * fmaxf(y2 - y1, 0.0f);
            float areaB = (Bv.z - Bv.x) * (Bv.w - Bv.y);
            float uni = areaA + areaB - inter;
            bool sup = (j > t) && (inter > NMS_T * uni);
            ull bit = sup ? (1ULL << (j & 63)) : 0ULL;
            if (j < 64)       m0 |= bit;
            else if (j < 128) m1 |= bit;
            else              m2 |= bit;
        }
        mk[t * 3 + 0] = m0; mk[t * 3 + 1] = m1; mk[t * 3 + 2] = m2;
    }
    __syncthreads();

    ull kp0 = (Mc <= 0) ? 0ULL : (Mc >= 64 ? ~0ULL : ((1ULL << Mc) - 1));
    int c1 = Mc - 64;
    ull kp1 = (c1 <= 0) ? 0ULL : (c1 >= 64 ? ~0ULL : ((1ULL << c1) - 1));
    int c2 = Mc - 128;
    ull kp2 = (c2 <= 0) ? 0ULL : (c2 >= 64 ? ~0ULL : ((1ULL << c2) - 1));

#pragma unroll 4
    for (int i = 0; i < Mc; i++) {
        ull m0 = mk[i * 3 + 0], m1 = mk[i * 3 + 1], m2 = mk[i * 3 + 2];
        ull kw = (i < 64) ? kp0 : (i < 128) ? kp1 : kp2;
        if ((kw >> (i & 63)) & 1ULL) {
            kp0 &= ~m0; kp1 &= ~m1; kp2 &= ~m2;
        }
    }

    for (int t = tid; t < M; t += 128) {
        int n = (int)(ks[t] & 0xFFFFFFFFULL);
        int idx = bIdx + n;
        ull kw = (t < 64) ? kp0 : (t < 128) ? kp1 : kp2;
        bool kept = (kw >> (t & 63)) & 1ULL;
        float s = __uint_as_float(~(unsigned)(ks[t] >> 32));
        float4 Bv = bx[t];
        out[idx * 5 + 0] = kept ? Bv.x : 0.0f;
        out[idx * 5 + 1] = kept ? Bv.y : 0.0f;
        out[idx * 5 + 2] = kept ? Bv.z : 0.0f;
        out[idx * 5 + 3] = kept ? Bv.w : 0.0f;
        out[idx * 5 + 4] = kept ? s : 0.0f;
        out[Bn * Nn * 6 + idx] = kept ? 1.0f : 0.0f;
    }
}

// ---------------- launch -----------------------------------------------------
extern "C" void kernel_launch(void* const* d_in, const int* in_sizes, int n_in,
                              void* d_out, int out_size)
{
    const float* feat = (const float*)d_in[0];
    const float* wo   = (const float*)d_in[1];
    const float* bo   = (const float*)d_in[2];
    const float* wc   = (const float*)d_in[3];
    const float* bc   = (const float*)d_in[4];
    const float* wr   = (const float*)d_in[5];
    const float* br   = (const float*)d_in[6];
    float* out = (float*)d_out;

    size_t smem = (size_t)F_TOTAL * sizeof(float);   // 57472 B
    cudaFuncSetAttribute(head_kernel,
                         cudaFuncAttributeMaxDynamicSharedMemorySize, (int)smem);

    head_kernel<<<400, TBH, smem>>>(feat, wo, bo, wc, bc, wr, br, out);
    nms_kernel<<<NGRP, 128>>>(out);
}